// round 2
// baseline (speedup 1.0000x reference)
#include <cuda_runtime.h>
#include <math.h>

#define B  32
#define T  20
#define C  512
#define P  196
#define H  1024
#define NC 101

// ---------------- device scratch (no allocations allowed) ----------------
__device__ float g_sA2pre[T * B * P];     // sum_c videos*W_sC21 + b_sC21 + spatialBias
__device__ float g_tC2pre[T * B * P];     // sum_c videos*W_tC21
__device__ float g_YT[C * B];             // Y transposed: [c][b]
__device__ float g_h1T[(T + 1) * H * B];  // h1 history, transposed [t][h][b]
__device__ float g_h2T[(T + 1) * H * B];  // h2 history, transposed [t][h][b]
__device__ float g_h2n[(T + 1) * B * H];  // h2 history, normal [t][b][h]
__device__ float g_c1[B * H];
__device__ float g_c2[B * H];
__device__ float g_beta[T * B];           // raw betas [t][b]
__device__ float g_betasT[B * T];         // softmaxed [b][t]
__device__ float g_hbarT[H * B];          // sum_t betasT*h2_t, transposed

__device__ __forceinline__ float sigm(float x) { return 1.0f / (1.0f + __expf(-x)); }
__device__ __forceinline__ float ftanh(float x) {
    // tanh(x) = 1 - 2/(exp(2x)+1); handles +/-inf limits correctly
    return 1.0f - 2.0f / (__expf(2.0f * x) + 1.0f);
}

// ---------------- init: broadcast (1,H) states to all batches ----------------
__global__ void init_kernel(const float* __restrict__ h1, const float* __restrict__ c1,
                            const float* __restrict__ h2, const float* __restrict__ c2) {
    int idx = blockIdx.x * blockDim.x + threadIdx.x;
    if (idx >= B * H) return;
    int b = idx / H, h = idx % H;
    g_h1T[h * B + b] = h1[h];
    g_h2T[h * B + b] = h2[h];
    g_h2n[b * H + h] = h2[h];
    g_c1[b * H + h]  = c1[h];
    g_c2[b * H + h]  = c2[h];
}

// ---------------- precompute sA2pre / tC2pre (one pass over videos) ----------------
__global__ void pre_kernel(const float* __restrict__ videos,
                           const float* __restrict__ W_s, const float* __restrict__ b_s,
                           const float* __restrict__ W_t, const float* __restrict__ spatialBias) {
    __shared__ float ws[C], wt[C];
    int tid = threadIdx.x;
    for (int c = tid; c < C; c += blockDim.x) { ws[c] = W_s[c]; wt[c] = W_t[c]; }
    __syncthreads();
    int bid = blockIdx.x;
    int b = bid / T, t = bid % T;
    int p = tid;
    if (p >= P) return;
    const float* vp = videos + ((size_t)(b * T + t) * C) * P + p;
    float accs = 0.f, acct = 0.f;
#pragma unroll 4
    for (int c = 0; c < C; c++) {
        float v = vp[(size_t)c * P];
        accs += v * ws[c];
        acct += v * wt[c];
    }
    int o = (t * B + b) * P + p;
    g_sA2pre[o] = accs + b_s[0] + spatialBias[p];
    g_tC2pre[o] = acct;
}

// ---------------- per-step attention: scores + softmax + beta ----------------
__global__ void attn_kernel(int t,
                            const float* __restrict__ W_h2p, const float* __restrict__ b_h2p,
                            const float* __restrict__ W_h21, const float* __restrict__ b_h21,
                            const float* __restrict__ b_tC21, const float* __restrict__ temporalBias,
                            float* __restrict__ alphas_out) {
    __shared__ float h2s[H];
    __shared__ float sc[P];
    __shared__ float red[8];
    int b = blockIdx.x, tid = threadIdx.x;
    int lane = tid & 31, w = tid >> 5;

    const float* h2p = g_h2n + (size_t)t * B * H + (size_t)b * H;
    for (int i = tid; i < H; i += 256) h2s[i] = h2p[i];
    __syncthreads();

    const float4* h4 = (const float4*)h2s;
    for (int p = w; p < P; p += 8) {
        const float4* wr = (const float4*)(W_h2p + (size_t)p * H);
        float acc = 0.f;
#pragma unroll
        for (int i = lane; i < H / 4; i += 32) {
            float4 a = wr[i], x = h4[i];
            acc += a.x * x.x + a.y * x.y + a.z * x.z + a.w * x.w;
        }
        for (int o = 16; o; o >>= 1) acc += __shfl_xor_sync(~0u, acc, o);
        if (lane == 0) sc[p] = acc + b_h2p[p] + g_sA2pre[(t * B + b) * P + p];
    }
    __syncthreads();

    // softmax over P
    float v = (tid < P) ? sc[tid] : -INFINITY;
    float m = v;
    for (int o = 16; o; o >>= 1) m = fmaxf(m, __shfl_xor_sync(~0u, m, o));
    if (lane == 0) red[w] = m;
    __syncthreads();
    m = red[0];
#pragma unroll
    for (int i = 1; i < 8; i++) m = fmaxf(m, red[i]);
    float e = (tid < P) ? __expf(v - m) : 0.f;
    float s = e;
    for (int o = 16; o; o >>= 1) s += __shfl_xor_sync(~0u, s, o);
    __syncthreads();
    if (lane == 0) red[w] = s;
    __syncthreads();
    s = red[0];
#pragma unroll
    for (int i = 1; i < 8; i++) s += red[i];
    float a = e / s;
    __syncthreads();
    if (tid < P) {
        sc[tid] = a;
        alphas_out[((size_t)t * B + b) * P + tid] = a;
    }
    __syncthreads();

    // beta = h2.W_h21 + dot(alpha, tC2pre) + consts
    float acc = 0.f;
    for (int i = tid; i < H; i += 256) acc += h2s[i] * W_h21[i];
    if (tid < P) acc += sc[tid] * g_tC2pre[(t * B + b) * P + tid];
    for (int o = 16; o; o >>= 1) acc += __shfl_xor_sync(~0u, acc, o);
    if (lane == 0) red[w] = acc;
    __syncthreads();
    if (tid == 0) {
        float sum = 0.f;
#pragma unroll
        for (int i = 0; i < 8; i++) sum += red[i];
        g_beta[t * B + b] = sum + b_h21[0] + b_tC21[0] + temporalBias[0];
    }
}

// ---------------- per-step Y[b,c] = sum_p alpha[b,p]*videos[b,t,c,p] ----------------
__global__ void y_kernel(int t, const float* __restrict__ videos, const float* __restrict__ alphas) {
    __shared__ float al[P];
    int b = blockIdx.y;
    int tid = threadIdx.x, lane = tid & 31, w = tid >> 5;
    for (int i = tid; i < P; i += 256) al[i] = alphas[((size_t)t * B + b) * P + i];
    __syncthreads();
    int c = blockIdx.x * 8 + w;
    const float* vp = videos + (((size_t)b * T + t) * C + c) * P;
    float acc = 0.f;
    for (int p = lane; p < P; p += 32) acc += al[p] * vp[p];
    for (int o = 16; o; o >>= 1) acc += __shfl_xor_sync(~0u, acc, o);
    if (lane == 0) g_YT[c * B + b] = acc;
}

// ---------------- fused LSTM gate + cell update: 1 warp per hidden unit, lane=batch ----
// MODE 0: LSTM1 (X1=YT K1=C, X2=h1T[t], out h1T[t+1], c1)
// MODE 1: LSTM2 (X1=h1T[t+1] K1=H, X2=h2T[t], out h2T[t+1]+h2n[t+1], c2)
template <int MODE>
__global__ void lstm_kernel(int t,
                            const float* __restrict__ Wih, const float* __restrict__ Whh,
                            const float* __restrict__ bih, const float* __restrict__ bhh) {
    constexpr int K1 = (MODE == 0) ? C : H;
    int h = blockIdx.x, lane = threadIdx.x;

    const float* X1 = (MODE == 0) ? g_YT : (g_h1T + (size_t)(t + 1) * H * B);
    const float* X2 = (MODE == 0) ? (g_h1T + (size_t)t * H * B) : (g_h2T + (size_t)t * H * B);
    float* cS = (MODE == 0) ? g_c1 : g_c2;

    float ai = bih[h]         + bhh[h];
    float af = bih[H + h]     + bhh[H + h];
    float ag = bih[2 * H + h] + bhh[2 * H + h];
    float ao = bih[3 * H + h] + bhh[3 * H + h];

    {
        const float4* wi = (const float4*)(Wih + (size_t)h * K1);
        const float4* wf = (const float4*)(Wih + (size_t)(H + h) * K1);
        const float4* wg = (const float4*)(Wih + (size_t)(2 * H + h) * K1);
        const float4* wo = (const float4*)(Wih + (size_t)(3 * H + h) * K1);
#pragma unroll 4
        for (int k4 = 0; k4 < K1 / 4; k4++) {
            float x0 = X1[(k4 * 4 + 0) * B + lane];
            float x1 = X1[(k4 * 4 + 1) * B + lane];
            float x2 = X1[(k4 * 4 + 2) * B + lane];
            float x3 = X1[(k4 * 4 + 3) * B + lane];
            float4 a = wi[k4]; ai += a.x * x0 + a.y * x1 + a.z * x2 + a.w * x3;
            float4 bq = wf[k4]; af += bq.x * x0 + bq.y * x1 + bq.z * x2 + bq.w * x3;
            float4 cq = wg[k4]; ag += cq.x * x0 + cq.y * x1 + cq.z * x2 + cq.w * x3;
            float4 dq = wo[k4]; ao += dq.x * x0 + dq.y * x1 + dq.z * x2 + dq.w * x3;
        }
    }
    {
        const float4* wi = (const float4*)(Whh + (size_t)h * H);
        const float4* wf = (const float4*)(Whh + (size_t)(H + h) * H);
        const float4* wg = (const float4*)(Whh + (size_t)(2 * H + h) * H);
        const float4* wo = (const float4*)(Whh + (size_t)(3 * H + h) * H);
#pragma unroll 4
        for (int k4 = 0; k4 < H / 4; k4++) {
            float x0 = X2[(k4 * 4 + 0) * B + lane];
            float x1 = X2[(k4 * 4 + 1) * B + lane];
            float x2 = X2[(k4 * 4 + 2) * B + lane];
            float x3 = X2[(k4 * 4 + 3) * B + lane];
            float4 a = wi[k4]; ai += a.x * x0 + a.y * x1 + a.z * x2 + a.w * x3;
            float4 bq = wf[k4]; af += bq.x * x0 + bq.y * x1 + bq.z * x2 + bq.w * x3;
            float4 cq = wg[k4]; ag += cq.x * x0 + cq.y * x1 + cq.z * x2 + cq.w * x3;
            float4 dq = wo[k4]; ao += dq.x * x0 + dq.y * x1 + dq.z * x2 + dq.w * x3;
        }
    }

    float i = sigm(ai);
    float f = sigm(af);
    float g = ftanh(ag);
    float o = sigm(ao);
    float c_old = cS[lane * H + h];
    float cn = f * c_old + i * g;
    float hn = o * ftanh(cn);
    cS[lane * H + h] = cn;
    if (MODE == 0) {
        g_h1T[(size_t)(t + 1) * H * B + h * B + lane] = hn;
    } else {
        g_h2T[(size_t)(t + 1) * H * B + h * B + lane] = hn;
        g_h2n[(size_t)(t + 1) * B * H + lane * H + h] = hn;
    }
}

// ---------------- betas softmax over time ----------------
__global__ void betasoft_kernel(float* __restrict__ betasT_out) {
    int b = threadIdx.x;  // 32 threads
    float v[T];
    float m = -INFINITY;
#pragma unroll
    for (int t = 0; t < T; t++) { v[t] = g_beta[t * B + b]; m = fmaxf(m, v[t]); }
    float s = 0.f;
#pragma unroll
    for (int t = 0; t < T; t++) { v[t] = __expf(v[t] - m); s += v[t]; }
    float inv = 1.f / s;
#pragma unroll
    for (int t = 0; t < T; t++) {
        float bt = v[t] * inv;
        g_betasT[b * T + t] = bt;
        betasT_out[b * T + t] = bt;
    }
}

// ---------------- hbar[b,:] = sum_t betasT[b,t] * h2_t[b,:] ----------------
__global__ void hbar_kernel() {
    int h = blockIdx.x, lane = threadIdx.x;
    float acc = 0.f;
#pragma unroll
    for (int t = 0; t < T; t++)
        acc += g_betasT[lane * T + t] * g_h2T[(size_t)(t + 1) * H * B + h * B + lane];
    g_hbarT[h * B + lane] = acc;
}

// ---------------- logits = hbar @ W_fc.T + b_fc ----------------
__global__ void logits_kernel(const float* __restrict__ W_fc, const float* __restrict__ b_fc,
                              float* __restrict__ out) {
    int nc = blockIdx.x, lane = threadIdx.x;
    float acc = b_fc[nc];
    const float4* wr = (const float4*)(W_fc + (size_t)nc * H);
#pragma unroll 4
    for (int k4 = 0; k4 < H / 4; k4++) {
        float4 a = wr[k4];
        acc += a.x * g_hbarT[(k4 * 4 + 0) * B + lane]
             + a.y * g_hbarT[(k4 * 4 + 1) * B + lane]
             + a.z * g_hbarT[(k4 * 4 + 2) * B + lane]
             + a.w * g_hbarT[(k4 * 4 + 3) * B + lane];
    }
    out[lane * NC + nc] = acc;
}

// ---------------- launch ----------------
extern "C" void kernel_launch(void* const* d_in, const int* in_sizes, int n_in,
                              void* d_out, int out_size) {
    const float* videos       = (const float*)d_in[0];
    const float* h1           = (const float*)d_in[1];
    const float* c1           = (const float*)d_in[2];
    const float* h2           = (const float*)d_in[3];
    const float* c2           = (const float*)d_in[4];
    const float* spatialBias  = (const float*)d_in[5];
    const float* temporalBias = (const float*)d_in[6];
    const float* W_h2p        = (const float*)d_in[7];
    const float* b_h2p        = (const float*)d_in[8];
    const float* W_sC21       = (const float*)d_in[9];
    const float* b_sC21       = (const float*)d_in[10];
    const float* W_h21        = (const float*)d_in[11];
    const float* b_h21        = (const float*)d_in[12];
    const float* W_tC21       = (const float*)d_in[13];
    const float* b_tC21       = (const float*)d_in[14];
    const float* Wih1         = (const float*)d_in[15];
    const float* Whh1         = (const float*)d_in[16];
    const float* bih1         = (const float*)d_in[17];
    const float* bhh1         = (const float*)d_in[18];
    const float* Wih2         = (const float*)d_in[19];
    const float* Whh2         = (const float*)d_in[20];
    const float* bih2         = (const float*)d_in[21];
    const float* bhh2         = (const float*)d_in[22];
    const float* W_fc         = (const float*)d_in[23];
    const float* b_fc         = (const float*)d_in[24];

    float* out        = (float*)d_out;
    float* logits_out = out;                                   // (B, NC)
    float* alphas_out = out + B * NC;                          // (T, B, P)
    float* betasT_out = out + B * NC + (size_t)T * B * P;      // (B, 1, T)

    init_kernel<<<(B * H + 255) / 256, 256>>>(h1, c1, h2, c2);
    pre_kernel<<<B * T, 224>>>(videos, W_sC21, b_sC21, W_tC21, spatialBias);

    for (int t = 0; t < T; t++) {
        attn_kernel<<<B, 256>>>(t, W_h2p, b_h2p, W_h21, b_h21, b_tC21, temporalBias, alphas_out);
        y_kernel<<<dim3(C / 8, B), 256>>>(t, videos, alphas_out);
        lstm_kernel<0><<<H, 32>>>(t, Wih1, Whh1, bih1, bhh1);
        lstm_kernel<1><<<H, 32>>>(t, Wih2, Whh2, bih2, bhh2);
    }

    betasoft_kernel<<<1, B>>>(betasT_out);
    hbar_kernel<<<H, 32>>>();
    logits_kernel<<<NC, 32>>>(W_fc, b_fc, logits_out);
}

// round 3
// speedup vs baseline: 2.4481x; 2.4481x over previous
#include <cuda_runtime.h>
#include <math.h>

#define B_  32
#define T_  20
#define C_  512
#define P_  196
#define H_  1024
#define NC_ 101
#define NBLK 148
#define NTHR 256

// ---------------- device scratch ----------------
__device__ float g_sA2pre[T_ * B_ * P_];
__device__ float g_tC2pre[T_ * B_ * P_];
__device__ float g_sc[B_ * P_];
__device__ float g_betaH[B_];
__device__ float g_YT[C_ * B_];
__device__ float g_h1T[2][H_ * B_];
__device__ float g_h2T[2][H_ * B_];
__device__ float g_h2n[B_ * H_];
__device__ float g_h2hist[T_ * H_ * B_];
__device__ float g_c1[H_ * B_];
__device__ float g_c2[H_ * B_];
__device__ float g_beta[T_ * B_];
__device__ float g_betasT[B_ * T_];
__device__ float g_hbarN[B_ * H_];
__device__ unsigned g_bar_cnt;
__device__ volatile unsigned g_bar_gen;

__device__ __forceinline__ float sigm(float x) { return 1.0f / (1.0f + __expf(-x)); }
__device__ __forceinline__ float ftanh(float x) { return 1.0f - 2.0f / (__expf(2.0f * x) + 1.0f); }
__device__ __forceinline__ float d4(float4 a, float4 b) {
    return a.x * b.x + a.y * b.y + a.z * b.z + a.w * b.w;
}

// software grid barrier (all NBLK blocks co-resident)
__device__ __forceinline__ void grid_sync() {
    __syncthreads();
    if (threadIdx.x == 0) {
        __threadfence();
        unsigned gen = g_bar_gen;
        if (atomicAdd(&g_bar_cnt, 1u) == (unsigned)(NBLK - 1)) {
            g_bar_cnt = 0;
            __threadfence();
            g_bar_gen = gen + 1;
        } else {
            while (g_bar_gen == gen) { __nanosleep(64); }
        }
        __threadfence();
    }
    __syncthreads();
}

// ---------------- fused LSTM gemm + cell phase ----------------
// MODE 0: X1=g_YT (K1=C), X2=h1T[t], out h1T[t+1], c1
// MODE 1: X1=h1T[t+1] (K1=H), X2=h2T[t], out h2T[t+1], h2n, h2hist[t], c2
template <int MODE>
__device__ void lstm_phase(int t,
                           const float* __restrict__ Wih, const float* __restrict__ Whh,
                           const float* __restrict__ bih, const float* __restrict__ bhh,
                           float* smem) {
    constexpr int K1 = (MODE == 0) ? C_ : H_;
    constexpr int K = K1 + H_;
    const int bid = blockIdx.x, tid = threadIdx.x;
    if (bid >= 128) return;
    const float* X1 = (MODE == 0) ? g_YT : g_h1T[(t + 1) & 1];
    const float* X2 = (MODE == 0) ? g_h1T[t & 1] : g_h2T[t & 1];

    float* Xs = smem;            // [128][34]
    float* Ws = smem + 128 * 34; // [32][132]

    const int h0 = bid * 8;
    const int half = tid >> 7;        // K-split half
    const int t128 = tid & 127;
    const int tx = t128 & 15, ty = t128 >> 4;
    const int b0 = tx * 2;

    float acc[4][2];
#pragma unroll
    for (int i = 0; i < 4; i++) {
        int l = ty * 4 + i;
        int row = (l >> 3) * H_ + h0 + (l & 7);
        float bv = (half == 0) ? (bih[row] + bhh[row]) : 0.f;
        acc[i][0] = bv; acc[i][1] = bv;
    }

    for (int kc = 0; kc < K; kc += 128) {
        // X tile: [128 k][32 b], pad to 34
#pragma unroll
        for (int i = 0; i < 16; i++) {
            int id = tid + 256 * i;
            int kk = id >> 5, b = id & 31;
            int kg = kc + kk;
            float x = (kg < K1) ? X1[kg * B_ + b] : X2[(kg - K1) * B_ + b];
            Xs[kk * 34 + b] = x;
        }
        // W tile: [32 rows][128 k] as float4, pad to 132
#pragma unroll
        for (int i = 0; i < 4; i++) {
            int id = tid + 256 * i;
            int l = id >> 5;
            int kq = id & 31;
            int kg = kc + kq * 4;
            int row = (l >> 3) * H_ + h0 + (l & 7);
            const float* src = (kg < K1) ? (Wih + (size_t)row * K1 + kg)
                                         : (Whh + (size_t)row * H_ + (kg - K1));
            *(float4*)&Ws[l * 132 + kq * 4] = *(const float4*)src;
        }
        __syncthreads();
        const int kb = half * 64;
#pragma unroll 4
        for (int kk = 0; kk < 64; kk += 4) {
            float4 wv[4];
#pragma unroll
            for (int i = 0; i < 4; i++)
                wv[i] = *(const float4*)&Ws[(ty * 4 + i) * 132 + kb + kk];
            float2 xv[4];
#pragma unroll
            for (int k = 0; k < 4; k++)
                xv[k] = *(const float2*)&Xs[(kb + kk + k) * 34 + b0];
#pragma unroll
            for (int i = 0; i < 4; i++) {
                acc[i][0] += wv[i].x * xv[0].x + wv[i].y * xv[1].x + wv[i].z * xv[2].x + wv[i].w * xv[3].x;
                acc[i][1] += wv[i].x * xv[0].y + wv[i].y * xv[1].y + wv[i].z * xv[2].y + wv[i].w * xv[3].y;
            }
        }
        __syncthreads();
    }

    // epilogue: combine K-halves in smem (aliases Xs), fused cell update
    float* Gs = smem;  // [2][32][33]
#pragma unroll
    for (int i = 0; i < 4; i++) {
        int l = ty * 4 + i;
        Gs[(half * 32 + l) * 33 + b0]     = acc[i][0];
        Gs[(half * 32 + l) * 33 + b0 + 1] = acc[i][1];
    }
    __syncthreads();
    {
        int hloc = tid >> 5, b = tid & 31;   // 8 h-units x 32 b
        float gi = Gs[(0 * 8 + hloc) * 33 + b] + Gs[(32 + 0 * 8 + hloc) * 33 + b];
        float gf = Gs[(1 * 8 + hloc) * 33 + b] + Gs[(32 + 1 * 8 + hloc) * 33 + b];
        float gg = Gs[(2 * 8 + hloc) * 33 + b] + Gs[(32 + 2 * 8 + hloc) * 33 + b];
        float go = Gs[(3 * 8 + hloc) * 33 + b] + Gs[(32 + 3 * 8 + hloc) * 33 + b];
        float i_ = sigm(gi), f_ = sigm(gf), gv = ftanh(gg), o_ = sigm(go);
        float* cS = (MODE == 0) ? g_c1 : g_c2;
        int hb = (h0 + hloc) * B_ + b;
        float cn = f_ * cS[hb] + i_ * gv;
        float hn = o_ * ftanh(cn);
        cS[hb] = cn;
        if (MODE == 0) {
            g_h1T[(t + 1) & 1][hb] = hn;
        } else {
            g_h2T[(t + 1) & 1][hb] = hn;
            g_h2n[b * H_ + h0 + hloc] = hn;
            g_h2hist[(size_t)t * H_ * B_ + hb] = hn;
        }
    }
    __syncthreads();
}

// ---------------- the single persistent kernel ----------------
__global__ void __launch_bounds__(NTHR, 1)
stdec_kernel(const float* __restrict__ videos,
             const float* __restrict__ h1in, const float* __restrict__ c1in,
             const float* __restrict__ h2in, const float* __restrict__ c2in,
             const float* __restrict__ spatialBias, const float* __restrict__ temporalBias,
             const float* __restrict__ W_h2p, const float* __restrict__ b_h2p,
             const float* __restrict__ W_sC21, const float* __restrict__ b_sC21,
             const float* __restrict__ W_h21, const float* __restrict__ b_h21,
             const float* __restrict__ W_tC21, const float* __restrict__ b_tC21,
             const float* __restrict__ Wih1, const float* __restrict__ Whh1,
             const float* __restrict__ bih1, const float* __restrict__ bhh1,
             const float* __restrict__ Wih2, const float* __restrict__ Whh2,
             const float* __restrict__ bih2, const float* __restrict__ bhh2,
             const float* __restrict__ W_fc, const float* __restrict__ b_fc,
             float* __restrict__ logits_out, float* __restrict__ alphas_out,
             float* __restrict__ betasT_out) {
    __shared__ __align__(16) float s_pool[128 * 34 + 32 * 132];
    const int bid = blockIdx.x, tid = threadIdx.x;
    const int lane = tid & 31, wid = tid >> 5;
    const int gw = bid * 8 + wid;  // global warp id

    // ---- init states ----
    for (int idx = bid * NTHR + tid; idx < H_ * B_; idx += NBLK * NTHR) {
        int h = idx >> 5, b = idx & 31;
        g_h1T[0][idx] = h1in[h];
        g_h2T[0][idx] = h2in[h];
        g_c1[idx] = c1in[h];
        g_c2[idx] = c2in[h];
        g_h2n[b * H_ + h] = h2in[h];
    }

    // ---- precompute sA2pre / tC2pre ----
    {
        float* ws = s_pool;
        float* wt = s_pool + 512;
        for (int i = tid; i < C_; i += NTHR) { ws[i] = W_sC21[i]; wt[i] = W_tC21[i]; }
        __syncthreads();
        float bs0 = b_sC21[0];
        for (int task = bid; task < B_ * T_; task += NBLK) {
            int b = task / T_, t = task % T_;
            if (tid < P_) {
                const float* vp = videos + ((size_t)(b * T_ + t) * C_) * P_ + tid;
                float accs = 0.f, acct = 0.f;
#pragma unroll 8
                for (int c = 0; c < C_; c++) {
                    float v = vp[(size_t)c * P_];
                    accs += v * ws[c];
                    acct += v * wt[c];
                }
                int o = (t * B_ + b) * P_ + tid;
                g_sA2pre[o] = accs + bs0 + spatialBias[tid];
                g_tC2pre[o] = acct;
            }
        }
        __syncthreads();
    }
    grid_sync();

    // ---- recurrence ----
    for (int t = 0; t < T_; t++) {
        // scores: warp per (b,p) dot; p==196 -> betaH
        for (int task = gw; task < B_ * 197; task += NBLK * 8) {
            int b = task / 197, p = task % 197;
            const float4* xr = (const float4*)(g_h2n + b * H_);
            const float4* wr = (const float4*)((p < P_) ? (W_h2p + (size_t)p * H_) : W_h21);
            float acc = 0.f;
#pragma unroll
            for (int j = 0; j < 8; j++) acc += d4(wr[lane + 32 * j], xr[lane + 32 * j]);
            for (int o = 16; o; o >>= 1) acc += __shfl_xor_sync(~0u, acc, o);
            if (lane == 0) {
                if (p < P_)
                    g_sc[b * P_ + p] = acc + b_h2p[p] + g_sA2pre[(t * B_ + b) * P_ + p];
                else
                    g_betaH[b] = acc;
            }
        }
        grid_sync();

        // softmax + alpha/beta out + Y  (blocks 0..127: b = bid>>2, c-chunk = bid&3)
        if (bid < 128) {
            float* sred = s_pool;          // [8]
            float* s_alpha = s_pool + 16;  // [196]
            int b = bid >> 2, chunk = bid & 3, c0 = chunk * 128;

            float v = (tid < P_) ? g_sc[b * P_ + tid] : -1e30f;
            float m = v;
            for (int o = 16; o; o >>= 1) m = fmaxf(m, __shfl_xor_sync(~0u, m, o));
            if (lane == 0) sred[wid] = m;
            __syncthreads();
            float mAll = sred[0];
#pragma unroll
            for (int i = 1; i < 8; i++) mAll = fmaxf(mAll, sred[i]);
            float e = (tid < P_) ? __expf(v - mAll) : 0.f;
            float s = e;
            for (int o = 16; o; o >>= 1) s += __shfl_xor_sync(~0u, s, o);
            __syncthreads();
            if (lane == 0) sred[wid] = s;
            __syncthreads();
            float sAll = sred[0];
#pragma unroll
            for (int i = 1; i < 8; i++) sAll += sred[i];
            float a = e / sAll;
            __syncthreads();
            if (tid < P_) {
                s_alpha[tid] = a;
                if (chunk == 0) alphas_out[((size_t)t * B_ + b) * P_ + tid] = a;
            }
            __syncthreads();

            if (chunk == 0) {
                // beta = betaH + dot(alpha, tC2pre) + consts
                float acc = (tid < P_) ? a * g_tC2pre[(t * B_ + b) * P_ + tid] : 0.f;
                for (int o = 16; o; o >>= 1) acc += __shfl_xor_sync(~0u, acc, o);
                if (lane == 0) sred[wid] = acc;
                __syncthreads();
                if (tid == 0) {
                    float sum = 0.f;
#pragma unroll
                    for (int i = 0; i < 8; i++) sum += sred[i];
                    g_beta[t * B_ + b] = sum + g_betaH[b] + b_h21[0] + b_tC21[0] + temporalBias[0];
                }
            }

            // Y: warp per c-row within this block's 128-c chunk
            for (int c = wid; c < 128; c += 8) {
                int cg = c0 + c;
                const float* vp = videos + (((size_t)b * T_ + t) * C_ + cg) * P_;
                float acc = 0.f;
                for (int p = lane; p < P_; p += 32) acc += s_alpha[p] * vp[p];
                for (int o = 16; o; o >>= 1) acc += __shfl_xor_sync(~0u, acc, o);
                if (lane == 0) g_YT[cg * B_ + b] = acc;
            }
            __syncthreads();
        }
        grid_sync();

        lstm_phase<0>(t, Wih1, Whh1, bih1, bhh1, s_pool);
        grid_sync();
        lstm_phase<1>(t, Wih2, Whh2, bih2, bhh2, s_pool);
        grid_sync();
    }

    // ---- betas softmax over time ----
    if (bid == 0 && tid < B_) {
        int b = tid;
        float v[T_];
        float m = -1e30f;
#pragma unroll
        for (int t = 0; t < T_; t++) { v[t] = g_beta[t * B_ + b]; m = fmaxf(m, v[t]); }
        float s = 0.f;
#pragma unroll
        for (int t = 0; t < T_; t++) { v[t] = __expf(v[t] - m); s += v[t]; }
        float inv = 1.f / s;
#pragma unroll
        for (int t = 0; t < T_; t++) {
            float bt = v[t] * inv;
            g_betasT[b * T_ + t] = bt;
            betasT_out[b * T_ + t] = bt;
        }
    }
    grid_sync();

    // ---- hbar[b][h] = sum_t betasT[b][t] * h2hist[t][h][b] ----
    for (int idx = bid * NTHR + tid; idx < H_ * B_; idx += NBLK * NTHR) {
        int h = idx >> 5, b = idx & 31;
        float acc = 0.f;
#pragma unroll
        for (int t = 0; t < T_; t++)
            acc += g_betasT[b * T_ + t] * g_h2hist[(size_t)t * H_ * B_ + h * B_ + b];
        g_hbarN[b * H_ + h] = acc;
    }
    grid_sync();

    // ---- logits: warp per (nc,b) dot over H ----
    for (int task = gw; task < NC_ * B_; task += NBLK * 8) {
        int nc = task / B_, b = task % B_;
        const float4* wr = (const float4*)(W_fc + (size_t)nc * H_);
        const float4* xr = (const float4*)(g_hbarN + (size_t)b * H_);
        float acc = 0.f;
#pragma unroll
        for (int j = 0; j < 8; j++) acc += d4(wr[lane + 32 * j], xr[lane + 32 * j]);
        for (int o = 16; o; o >>= 1) acc += __shfl_xor_sync(~0u, acc, o);
        if (lane == 0) logits_out[b * NC_ + nc] = acc + b_fc[nc];
    }
}

// ---------------- launch ----------------
extern "C" void kernel_launch(void* const* d_in, const int* in_sizes, int n_in,
                              void* d_out, int out_size) {
    const float* videos       = (const float*)d_in[0];
    const float* h1           = (const float*)d_in[1];
    const float* c1           = (const float*)d_in[2];
    const float* h2           = (const float*)d_in[3];
    const float* c2           = (const float*)d_in[4];
    const float* spatialBias  = (const float*)d_in[5];
    const float* temporalBias = (const float*)d_in[6];
    const float* W_h2p        = (const float*)d_in[7];
    const float* b_h2p        = (const float*)d_in[8];
    const float* W_sC21       = (const float*)d_in[9];
    const float* b_sC21       = (const float*)d_in[10];
    const float* W_h21        = (const float*)d_in[11];
    const float* b_h21        = (const float*)d_in[12];
    const float* W_tC21       = (const float*)d_in[13];
    const float* b_tC21       = (const float*)d_in[14];
    const float* Wih1         = (const float*)d_in[15];
    const float* Whh1         = (const float*)d_in[16];
    const float* bih1         = (const float*)d_in[17];
    const float* bhh1         = (const float*)d_in[18];
    const float* Wih2         = (const float*)d_in[19];
    const float* Whh2         = (const float*)d_in[20];
    const float* bih2         = (const float*)d_in[21];
    const float* bhh2         = (const float*)d_in[22];
    const float* W_fc         = (const float*)d_in[23];
    const float* b_fc         = (const float*)d_in[24];

    float* out        = (float*)d_out;
    float* logits_out = out;
    float* alphas_out = out + B_ * NC_;
    float* betasT_out = out + B_ * NC_ + (size_t)T_ * B_ * P_;

    stdec_kernel<<<NBLK, NTHR>>>(videos, h1, c1, h2, c2, spatialBias, temporalBias,
                                 W_h2p, b_h2p, W_sC21, b_sC21, W_h21, b_h21, W_tC21, b_tC21,
                                 Wih1, Whh1, bih1, bhh1, Wih2, Whh2, bih2, bhh2,
                                 W_fc, b_fc, logits_out, alphas_out, betasT_out);
}

// round 4
// speedup vs baseline: 2.8782x; 1.1757x over previous
#include <cuda_runtime.h>
#include <math.h>

#define B_  32
#define T_  20
#define C_  512
#define P_  196
#define H_  1024
#define NC_ 101
#define NBLK 148
#define NTHR 256

// LSTM GEMM tiling
#define CHK 64                    // k per chunk
#define XSTR 36                   // X tile row stride (floats)
#define WSTR 68                   // W tile row stride (floats)
#define XSZ (CHK * XSTR)          // 2304 floats
#define WSZ (32 * WSTR)           // 2176 floats
#define GRPSZ (XSZ + WSZ)         // 4480 floats per group
#define BUFSZ (4 * GRPSZ)         // 17920 floats per buffer
#define SMEM_FLOATS (2 * BUFSZ)   // 35840 floats = 143360 bytes
#define SMEM_BYTES (SMEM_FLOATS * 4)

// ---------------- device scratch ----------------
__device__ float g_sA2pre[T_ * B_ * P_];
__device__ float g_tC2pre[T_ * B_ * P_];
__device__ float g_sc[B_ * P_];
__device__ float g_betaH[B_];
__device__ float g_YT[C_ * B_];
__device__ float g_h1T[2][H_ * B_];
__device__ float g_h2T[2][H_ * B_];
__device__ float g_h2n[B_ * H_];
__device__ float g_h2hist[T_ * H_ * B_];
__device__ float g_c1[H_ * B_];
__device__ float g_c2[H_ * B_];
__device__ float g_beta[T_ * B_];
__device__ float g_betasT[B_ * T_];
__device__ float g_hbarN[B_ * H_];
__device__ unsigned g_bar_cnt;
__device__ volatile unsigned g_bar_gen;

__device__ __forceinline__ float sigm(float x) { return 1.0f / (1.0f + __expf(-x)); }
__device__ __forceinline__ float ftanh(float x) { return 1.0f - 2.0f / (__expf(2.0f * x) + 1.0f); }
__device__ __forceinline__ float d4(float4 a, float4 b) {
    return a.x * b.x + a.y * b.y + a.z * b.z + a.w * b.w;
}

__device__ __forceinline__ void cp16(float* dst, const float* src) {
    unsigned u = (unsigned)__cvta_generic_to_shared(dst);
    asm volatile("cp.async.cg.shared.global [%0], [%1], 16;" :: "r"(u), "l"(src));
}
__device__ __forceinline__ void cp_commit() {
    asm volatile("cp.async.commit_group;" ::: "memory");
}
__device__ __forceinline__ void cp_wait1() {
    asm volatile("cp.async.wait_group 1;" ::: "memory");
}
__device__ __forceinline__ void cp_wait0() {
    asm volatile("cp.async.wait_group 0;" ::: "memory");
}

// software grid barrier (all NBLK blocks co-resident)
__device__ __forceinline__ void grid_sync() {
    __syncthreads();
    if (threadIdx.x == 0) {
        __threadfence();
        unsigned gen = g_bar_gen;
        if (atomicAdd(&g_bar_cnt, 1u) == (unsigned)(NBLK - 1)) {
            g_bar_cnt = 0;
            __threadfence();
            g_bar_gen = gen + 1;
        } else {
            while (g_bar_gen == gen) { __nanosleep(64); }
        }
        __threadfence();
    }
    __syncthreads();
}

// ---------------- fused LSTM gemm + cell phase ----------------
// 128 blocks; block handles 8 h-units (32 gate-rows) x 32 batch, 4-way K-split,
// thread tile 4 rows x 4 batch, cp.async double-buffered chunks of 64 k.
// MODE 0: X1=g_YT (K1=C), X2=h1T[t], out h1T[t+1], c1
// MODE 1: X1=h1T[t+1] (K1=H), X2=h2T[t], out h2T[t+1], h2n, h2hist[t], c2
template <int MODE>
__device__ void lstm_phase(int t,
                           const float* __restrict__ Wih, const float* __restrict__ Whh,
                           const float* __restrict__ bih, const float* __restrict__ bhh,
                           float* dsm) {
    constexpr int K1 = (MODE == 0) ? C_ : H_;
    constexpr int K = K1 + H_;
    constexpr int KG = K / 4;        // k per group
    constexpr int NCH = KG / CHK;    // chunks (6 or 8)
    const int bid = blockIdx.x, tid = threadIdx.x;
    if (bid >= 128) return;
    const float* __restrict__ X1 = (MODE == 0) ? g_YT : g_h1T[(t + 1) & 1];
    const float* __restrict__ X2 = (MODE == 0) ? g_h1T[t & 1] : g_h2T[t & 1];

    const int h0 = bid * 8;
    const int g = tid >> 6;          // k-group 0..3
    const int tg = tid & 63;
    const int tx = tg & 7;           // batch quad
    const int ty = tg >> 3;          // row base 0..7

    float acc[4][4];
#pragma unroll
    for (int i = 0; i < 4; i++)
#pragma unroll
        for (int j = 0; j < 4; j++) acc[i][j] = 0.f;

    // chunk loader: 8 X float4 + 8 W float4 per thread via cp.async
    auto load_chunk = [&](int c, int buf) {
        float* Xp = dsm + buf * BUFSZ + g * GRPSZ;
        float* Wp = Xp + XSZ;
        const int kbase = g * KG + c * CHK;
#pragma unroll
        for (int i = 0; i < 8; i++) {
            int f = tg + 64 * i;
            int kk = f >> 3, bq = f & 7;
            int kglob = kbase + kk;
            const float* src = (kglob < K1) ? (X1 + kglob * B_ + bq * 4)
                                            : (X2 + (kglob - K1) * B_ + bq * 4);
            cp16(Xp + kk * XSTR + bq * 4, src);
        }
#pragma unroll
        for (int i = 0; i < 8; i++) {
            int f = tg + 64 * i;
            int l = f >> 4, kq = f & 15;
            int kglob = kbase + kq * 4;
            int row = (l >> 3) * H_ + h0 + (l & 7);
            const float* src = (kglob < K1) ? (Wih + (size_t)row * K1 + kglob)
                                            : (Whh + (size_t)row * H_ + (kglob - K1));
            cp16(Wp + l * WSTR + kq * 4, src);
        }
    };

    load_chunk(0, 0);
    cp_commit();

    for (int c = 0; c < NCH; c++) {
        if (c + 1 < NCH) {
            load_chunk(c + 1, (c + 1) & 1);
            cp_commit();
            cp_wait1();
        } else {
            cp_commit();  // empty group keeps wait counts simple
            cp_wait0();
        }
        __syncthreads();

        const float* Xp = dsm + (c & 1) * BUFSZ + g * GRPSZ;
        const float* Wp = Xp + XSZ;
#pragma unroll 4
        for (int kk = 0; kk < CHK; kk += 4) {
            float4 wv[4], xv[4];
#pragma unroll
            for (int i = 0; i < 4; i++)
                wv[i] = *(const float4*)&Wp[(ty + 8 * i) * WSTR + kk];
#pragma unroll
            for (int r = 0; r < 4; r++)
                xv[r] = *(const float4*)&Xp[(kk + r) * XSTR + tx * 4];
#pragma unroll
            for (int i = 0; i < 4; i++) {
                acc[i][0] += wv[i].x * xv[0].x + wv[i].y * xv[1].x + wv[i].z * xv[2].x + wv[i].w * xv[3].x;
                acc[i][1] += wv[i].x * xv[0].y + wv[i].y * xv[1].y + wv[i].z * xv[2].y + wv[i].w * xv[3].y;
                acc[i][2] += wv[i].x * xv[0].z + wv[i].y * xv[1].z + wv[i].z * xv[2].z + wv[i].w * xv[3].z;
                acc[i][3] += wv[i].x * xv[0].w + wv[i].y * xv[1].w + wv[i].z * xv[2].w + wv[i].w * xv[3].w;
            }
        }
        __syncthreads();
    }

    // partial reduce across 4 k-groups (Gs aliases buffer 0)
    float* Gs = dsm;  // [4][32][32]
#pragma unroll
    for (int i = 0; i < 4; i++)
        *(float4*)&Gs[g * 1024 + (ty + 8 * i) * 32 + tx * 4] =
            make_float4(acc[i][0], acc[i][1], acc[i][2], acc[i][3]);
    __syncthreads();

    {
        int hloc = tid >> 5, b = tid & 31;
        float gate[4];
#pragma unroll
        for (int q = 0; q < 4; q++) {
            int l = q * 8 + hloc;
            int row = q * H_ + h0 + hloc;
            float s = bih[row] + bhh[row];
#pragma unroll
            for (int gg = 0; gg < 4; gg++) s += Gs[gg * 1024 + l * 32 + b];
            gate[q] = s;
        }
        float i_ = sigm(gate[0]), f_ = sigm(gate[1]), gv = ftanh(gate[2]), o_ = sigm(gate[3]);
        float* cS = (MODE == 0) ? g_c1 : g_c2;
        int hb = (h0 + hloc) * B_ + b;
        float cn = f_ * cS[hb] + i_ * gv;
        float hn = o_ * ftanh(cn);
        cS[hb] = cn;
        if (MODE == 0) {
            g_h1T[(t + 1) & 1][hb] = hn;
        } else {
            g_h2T[(t + 1) & 1][hb] = hn;
            g_h2n[b * H_ + h0 + hloc] = hn;
            g_h2hist[(size_t)t * H_ * B_ + hb] = hn;
        }
    }
    __syncthreads();
}

// ---------------- the single persistent kernel ----------------
__global__ void __launch_bounds__(NTHR, 1)
stdec_kernel(const float* __restrict__ videos,
             const float* __restrict__ h1in, const float* __restrict__ c1in,
             const float* __restrict__ h2in, const float* __restrict__ c2in,
             const float* __restrict__ spatialBias, const float* __restrict__ temporalBias,
             const float* __restrict__ W_h2p, const float* __restrict__ b_h2p,
             const float* __restrict__ W_sC21, const float* __restrict__ b_sC21,
             const float* __restrict__ W_h21, const float* __restrict__ b_h21,
             const float* __restrict__ W_tC21, const float* __restrict__ b_tC21,
             const float* __restrict__ Wih1, const float* __restrict__ Whh1,
             const float* __restrict__ bih1, const float* __restrict__ bhh1,
             const float* __restrict__ Wih2, const float* __restrict__ Whh2,
             const float* __restrict__ bih2, const float* __restrict__ bhh2,
             const float* __restrict__ W_fc, const float* __restrict__ b_fc,
             float* __restrict__ logits_out, float* __restrict__ alphas_out,
             float* __restrict__ betasT_out) {
    extern __shared__ __align__(16) float dsm[];
    const int bid = blockIdx.x, tid = threadIdx.x;
    const int lane = tid & 31, wid = tid >> 5;
    const int gw = bid * 8 + wid;  // global warp id

    // ---- init states ----
    for (int idx = bid * NTHR + tid; idx < H_ * B_; idx += NBLK * NTHR) {
        int h = idx >> 5, b = idx & 31;
        g_h1T[0][idx] = h1in[h];
        g_h2T[0][idx] = h2in[h];
        g_c1[idx] = c1in[h];
        g_c2[idx] = c2in[h];
        g_h2n[b * H_ + h] = h2in[h];
    }

    // ---- precompute sA2pre / tC2pre ----
    {
        float* ws = dsm;
        float* wt = dsm + C_;
        for (int i = tid; i < C_; i += NTHR) { ws[i] = W_sC21[i]; wt[i] = W_tC21[i]; }
        __syncthreads();
        float bs0 = b_sC21[0];
        for (int task = bid; task < B_ * T_; task += NBLK) {
            int b = task / T_, t = task % T_;
            if (tid < P_) {
                const float* vp = videos + ((size_t)(b * T_ + t) * C_) * P_ + tid;
                float accs = 0.f, acct = 0.f;
#pragma unroll 8
                for (int c = 0; c < C_; c++) {
                    float v = vp[(size_t)c * P_];
                    accs += v * ws[c];
                    acct += v * wt[c];
                }
                int o = (t * B_ + b) * P_ + tid;
                g_sA2pre[o] = accs + bs0 + spatialBias[tid];
                g_tC2pre[o] = acct;
            }
        }
        __syncthreads();
    }
    grid_sync();

    // ---- recurrence ----
    for (int t = 0; t < T_; t++) {
        // scores: warp per (b,p) dot; p==196 -> betaH
        for (int task = gw; task < B_ * 197; task += NBLK * 8) {
            int b = task / 197, p = task % 197;
            const float4* xr = (const float4*)(g_h2n + b * H_);
            const float4* wr = (const float4*)((p < P_) ? (W_h2p + (size_t)p * H_) : W_h21);
            float acc = 0.f;
#pragma unroll
            for (int j = 0; j < 8; j++) acc += d4(wr[lane + 32 * j], xr[lane + 32 * j]);
            for (int o = 16; o; o >>= 1) acc += __shfl_xor_sync(~0u, acc, o);
            if (lane == 0) {
                if (p < P_)
                    g_sc[b * P_ + p] = acc + b_h2p[p] + g_sA2pre[(t * B_ + b) * P_ + p];
                else
                    g_betaH[b] = acc;
            }
        }
        grid_sync();

        // softmax + alpha/beta out + Y  (blocks 0..127: b = bid>>2, c-chunk = bid&3)
        if (bid < 128) {
            float* sred = dsm;          // [8]
            float* s_alpha = dsm + 16;  // [196]
            int b = bid >> 2, chunk = bid & 3, c0 = chunk * 128;

            float v = (tid < P_) ? g_sc[b * P_ + tid] : -1e30f;
            float m = v;
            for (int o = 16; o; o >>= 1) m = fmaxf(m, __shfl_xor_sync(~0u, m, o));
            if (lane == 0) sred[wid] = m;
            __syncthreads();
            float mAll = sred[0];
#pragma unroll
            for (int i = 1; i < 8; i++) mAll = fmaxf(mAll, sred[i]);
            float e = (tid < P_) ? __expf(v - mAll) : 0.f;
            float s = e;
            for (int o = 16; o; o >>= 1) s += __shfl_xor_sync(~0u, s, o);
            __syncthreads();
            if (lane == 0) sred[wid] = s;
            __syncthreads();
            float sAll = sred[0];
#pragma unroll
            for (int i = 1; i < 8; i++) sAll += sred[i];
            float a = e / sAll;
            __syncthreads();
            if (tid < P_) {
                s_alpha[tid] = a;
                if (chunk == 0) alphas_out[((size_t)t * B_ + b) * P_ + tid] = a;
            }
            __syncthreads();

            if (chunk == 0) {
                float acc = (tid < P_) ? a * g_tC2pre[(t * B_ + b) * P_ + tid] : 0.f;
                for (int o = 16; o; o >>= 1) acc += __shfl_xor_sync(~0u, acc, o);
                if (lane == 0) sred[wid] = acc;
                __syncthreads();
                if (tid == 0) {
                    float sum = 0.f;
#pragma unroll
                    for (int i = 0; i < 8; i++) sum += sred[i];
                    g_beta[t * B_ + b] = sum + g_betaH[b] + b_h21[0] + b_tC21[0] + temporalBias[0];
                }
            }

            // Y: warp per c-row within this block's 128-c chunk
            for (int c = wid; c < 128; c += 8) {
                int cg = c0 + c;
                const float* vp = videos + (((size_t)b * T_ + t) * C_ + cg) * P_;
                float acc = 0.f;
                for (int p = lane; p < P_; p += 32) acc += s_alpha[p] * vp[p];
                for (int o = 16; o; o >>= 1) acc += __shfl_xor_sync(~0u, acc, o);
                if (lane == 0) g_YT[cg * B_ + b] = acc;
            }
            __syncthreads();
        }
        grid_sync();

        lstm_phase<0>(t, Wih1, Whh1, bih1, bhh1, dsm);
        grid_sync();
        lstm_phase<1>(t, Wih2, Whh2, bih2, bhh2, dsm);
        grid_sync();
    }

    // ---- betas softmax over time ----
    if (bid == 0 && tid < B_) {
        int b = tid;
        float v[T_];
        float m = -1e30f;
#pragma unroll
        for (int t = 0; t < T_; t++) { v[t] = g_beta[t * B_ + b]; m = fmaxf(m, v[t]); }
        float s = 0.f;
#pragma unroll
        for (int t = 0; t < T_; t++) { v[t] = __expf(v[t] - m); s += v[t]; }
        float inv = 1.f / s;
#pragma unroll
        for (int t = 0; t < T_; t++) {
            float bt = v[t] * inv;
            g_betasT[b * T_ + t] = bt;
            betasT_out[b * T_ + t] = bt;
        }
    }
    grid_sync();

    // ---- hbar[b][h] = sum_t betasT[b][t] * h2hist[t][h][b] ----
    for (int idx = bid * NTHR + tid; idx < H_ * B_; idx += NBLK * NTHR) {
        int h = idx >> 5, b = idx & 31;
        float acc = 0.f;
#pragma unroll
        for (int t = 0; t < T_; t++)
            acc += g_betasT[b * T_ + t] * g_h2hist[(size_t)t * H_ * B_ + h * B_ + b];
        g_hbarN[b * H_ + h] = acc;
    }
    grid_sync();

    // ---- logits: warp per (nc,b) dot over H ----
    for (int task = gw; task < NC_ * B_; task += NBLK * 8) {
        int nc = task / B_, b = task % B_;
        const float4* wr = (const float4*)(W_fc + (size_t)nc * H_);
        const float4* xr = (const float4*)(g_hbarN + (size_t)b * H_);
        float acc = 0.f;
#pragma unroll
        for (int j = 0; j < 8; j++) acc += d4(wr[lane + 32 * j], xr[lane + 32 * j]);
        for (int o = 16; o; o >>= 1) acc += __shfl_xor_sync(~0u, acc, o);
        if (lane == 0) logits_out[b * NC_ + nc] = acc + b_fc[nc];
    }
}

// ---------------- launch ----------------
extern "C" void kernel_launch(void* const* d_in, const int* in_sizes, int n_in,
                              void* d_out, int out_size) {
    const float* videos       = (const float*)d_in[0];
    const float* h1           = (const float*)d_in[1];
    const float* c1           = (const float*)d_in[2];
    const float* h2           = (const float*)d_in[3];
    const float* c2           = (const float*)d_in[4];
    const float* spatialBias  = (const float*)d_in[5];
    const float* temporalBias = (const float*)d_in[6];
    const float* W_h2p        = (const float*)d_in[7];
    const float* b_h2p        = (const float*)d_in[8];
    const float* W_sC21       = (const float*)d_in[9];
    const float* b_sC21       = (const float*)d_in[10];
    const float* W_h21        = (const float*)d_in[11];
    const float* b_h21        = (const float*)d_in[12];
    const float* W_tC21       = (const float*)d_in[13];
    const float* b_tC21       = (const float*)d_in[14];
    const float* Wih1         = (const float*)d_in[15];
    const float* Whh1         = (const float*)d_in[16];
    const float* bih1         = (const float*)d_in[17];
    const float* bhh1         = (const float*)d_in[18];
    const float* Wih2         = (const float*)d_in[19];
    const float* Whh2         = (const float*)d_in[20];
    const float* bih2         = (const float*)d_in[21];
    const float* bhh2         = (const float*)d_in[22];
    const float* W_fc         = (const float*)d_in[23];
    const float* b_fc         = (const float*)d_in[24];

    float* out        = (float*)d_out;
    float* logits_out = out;
    float* alphas_out = out + B_ * NC_;
    float* betasT_out = out + B_ * NC_ + (size_t)T_ * B_ * P_;

    cudaFuncSetAttribute(stdec_kernel, cudaFuncAttributeMaxDynamicSharedMemorySize, SMEM_BYTES);
    stdec_kernel<<<NBLK, NTHR, SMEM_BYTES>>>(videos, h1, c1, h2, c2, spatialBias, temporalBias,
                                 W_h2p, b_h2p, W_sC21, b_sC21, W_h21, b_h21, W_tC21, b_tC21,
                                 Wih1, Whh1, bih1, bhh1, Wih2, Whh2, bih2, bhh2,
                                 W_fc, b_fc, logits_out, alphas_out, betasT_out);
}

// round 5
// speedup vs baseline: 3.8985x; 1.3545x over previous
#include <cuda_runtime.h>
#include <math.h>

#define B_  32
#define T_  20
#define C_  512
#define P_  196
#define H_  1024
#define NC_ 101
#define NBLK 148
#define NTHR 512
#define NWRP (NTHR / 32)

// LSTM GEMM tiling: 8 k-groups x 64 threads, chunk = 32 k, double-buffered
#define NGRP 8
#define CHK 32
#define XSTR 36                   // X tile row stride (floats)
#define WSTR 36                   // W tile row stride (floats)
#define XSZ (CHK * XSTR)          // 1152
#define WSZ (32 * WSTR)           // 1152
#define GRPSZ (XSZ + WSZ)         // 2304
#define BUFSZ (NGRP * GRPSZ)      // 18432
#define SMEM_FLOATS (2 * BUFSZ)   // 36864 floats
#define SMEM_BYTES (SMEM_FLOATS * 4)  // 147456 B

// ---------------- device scratch ----------------
__device__ float g_sA2pre[T_ * B_ * P_];
__device__ float g_tC2pre[T_ * B_ * P_];
__device__ float g_sc[B_ * P_];
__device__ float g_betaH[B_];
__device__ float g_YT[C_ * B_];
__device__ float g_h1T[2][H_ * B_];
__device__ float g_h2T[2][H_ * B_];
__device__ float g_h2n[B_ * H_];
__device__ float g_h2hist[T_ * H_ * B_];
__device__ float g_c1[H_ * B_];
__device__ float g_c2[H_ * B_];
__device__ float g_beta[T_ * B_];
__device__ float g_betasT[B_ * T_];
__device__ float g_hbarN[B_ * H_];
__device__ unsigned g_bar_cnt;
__device__ volatile unsigned g_bar_gen;

__device__ __forceinline__ float sigm(float x) { return 1.0f / (1.0f + __expf(-x)); }
__device__ __forceinline__ float ftanh(float x) { return 1.0f - 2.0f / (__expf(2.0f * x) + 1.0f); }
__device__ __forceinline__ float d4(float4 a, float4 b) {
    return a.x * b.x + a.y * b.y + a.z * b.z + a.w * b.w;
}

__device__ __forceinline__ void cp16(float* dst, const float* src) {
    unsigned u = (unsigned)__cvta_generic_to_shared(dst);
    asm volatile("cp.async.cg.shared.global [%0], [%1], 16;" :: "r"(u), "l"(src));
}
__device__ __forceinline__ void cp_commit() {
    asm volatile("cp.async.commit_group;" ::: "memory");
}
__device__ __forceinline__ void cp_wait1() {
    asm volatile("cp.async.wait_group 1;" ::: "memory");
}
__device__ __forceinline__ void cp_wait0() {
    asm volatile("cp.async.wait_group 0;" ::: "memory");
}

// software grid barrier (all NBLK blocks co-resident)
__device__ __forceinline__ void grid_sync() {
    __syncthreads();
    if (threadIdx.x == 0) {
        __threadfence();
        unsigned gen = g_bar_gen;
        if (atomicAdd(&g_bar_cnt, 1u) == (unsigned)(NBLK - 1)) {
            g_bar_cnt = 0;
            __threadfence();
            g_bar_gen = gen + 1;
        } else {
            while (g_bar_gen == gen) { __nanosleep(64); }
        }
        __threadfence();
    }
    __syncthreads();
}

// ---------------- fused LSTM gemm + cell phase ----------------
// 128 blocks; block: 8 h-units (32 gate-rows) x 32 batch; 8-way K-split,
// thread tile 4 rows x 4 batch, cp.async double-buffered chunks of 32 k.
template <int MODE>
__device__ void lstm_phase(int t,
                           const float* __restrict__ Wih, const float* __restrict__ Whh,
                           const float* __restrict__ bih, const float* __restrict__ bhh,
                           float* dsm) {
    constexpr int K1 = (MODE == 0) ? C_ : H_;
    constexpr int K = K1 + H_;
    constexpr int KG = K / NGRP;     // 192 or 256
    constexpr int NCH = KG / CHK;    // 6 or 8
    const int bid = blockIdx.x, tid = threadIdx.x;
    if (bid >= 128) return;
    const float* __restrict__ X1 = (MODE == 0) ? g_YT : g_h1T[(t + 1) & 1];
    const float* __restrict__ X2 = (MODE == 0) ? g_h1T[t & 1] : g_h2T[t & 1];

    const int h0 = bid * 8;
    const int g = tid >> 6;          // k-group 0..7
    const int tg = tid & 63;
    const int tx = tg & 7;           // batch quad
    const int ty = tg >> 3;          // h-unit 0..7

    float acc[4][4];
#pragma unroll
    for (int i = 0; i < 4; i++)
#pragma unroll
        for (int j = 0; j < 4; j++) acc[i][j] = 0.f;

    // chunk loader: 4 X float4 + 4 W float4 per thread
    auto load_chunk = [&](int c, int buf) {
        float* Xp = dsm + buf * BUFSZ + g * GRPSZ;
        float* Wp = Xp + XSZ;
        const int kbase = g * KG + c * CHK;
#pragma unroll
        for (int i = 0; i < 4; i++) {
            int f = tg + 64 * i;
            int kk = f >> 3, bq = f & 7;
            int kglob = kbase + kk;
            const float* src = (kglob < K1) ? (X1 + kglob * B_ + bq * 4)
                                            : (X2 + (kglob - K1) * B_ + bq * 4);
            cp16(Xp + kk * XSTR + bq * 4, src);
        }
#pragma unroll
        for (int i = 0; i < 4; i++) {
            int f = tg + 64 * i;
            int l = f >> 3, kq = f & 7;
            int kglob = kbase + kq * 4;
            int row = (l >> 3) * H_ + h0 + (l & 7);
            const float* src = (kglob < K1) ? (Wih + (size_t)row * K1 + kglob)
                                            : (Whh + (size_t)row * H_ + (kglob - K1));
            cp16(Wp + l * WSTR + kq * 4, src);
        }
    };

    load_chunk(0, 0);
    cp_commit();

    for (int c = 0; c < NCH; c++) {
        if (c + 1 < NCH) {
            load_chunk(c + 1, (c + 1) & 1);
            cp_commit();
            cp_wait1();
        } else {
            cp_commit();
            cp_wait0();
        }
        __syncthreads();

        const float* Xp = dsm + (c & 1) * BUFSZ + g * GRPSZ;
        const float* Wp = Xp + XSZ;
#pragma unroll
        for (int kk = 0; kk < CHK; kk += 4) {
            float4 wv[4], xv[4];
#pragma unroll
            for (int i = 0; i < 4; i++)
                wv[i] = *(const float4*)&Wp[(ty + 8 * i) * WSTR + kk];
#pragma unroll
            for (int r = 0; r < 4; r++)
                xv[r] = *(const float4*)&Xp[(kk + r) * XSTR + tx * 4];
#pragma unroll
            for (int i = 0; i < 4; i++) {
                acc[i][0] += wv[i].x * xv[0].x + wv[i].y * xv[1].x + wv[i].z * xv[2].x + wv[i].w * xv[3].x;
                acc[i][1] += wv[i].x * xv[0].y + wv[i].y * xv[1].y + wv[i].z * xv[2].y + wv[i].w * xv[3].y;
                acc[i][2] += wv[i].x * xv[0].z + wv[i].y * xv[1].z + wv[i].z * xv[2].z + wv[i].w * xv[3].z;
                acc[i][3] += wv[i].x * xv[0].w + wv[i].y * xv[1].w + wv[i].z * xv[2].w + wv[i].w * xv[3].w;
            }
        }
        __syncthreads();
    }

    // partial reduce across 8 k-groups (Gs aliases buffers)
    float* Gs = dsm;  // [8][32][32]
#pragma unroll
    for (int i = 0; i < 4; i++)
        *(float4*)&Gs[g * 1024 + (ty + 8 * i) * 32 + tx * 4] =
            make_float4(acc[i][0], acc[i][1], acc[i][2], acc[i][3]);
    __syncthreads();

    if (tid < 256) {
        int hloc = tid >> 5, b = tid & 31;
        float gate[4];
#pragma unroll
        for (int q = 0; q < 4; q++) {
            int l = q * 8 + hloc;
            int row = q * H_ + h0 + hloc;
            float s = bih[row] + bhh[row];
#pragma unroll
            for (int gg = 0; gg < NGRP; gg++) s += Gs[gg * 1024 + l * 32 + b];
            gate[q] = s;
        }
        float i_ = sigm(gate[0]), f_ = sigm(gate[1]), gv = ftanh(gate[2]), o_ = sigm(gate[3]);
        float* cS = (MODE == 0) ? g_c1 : g_c2;
        int hb = (h0 + hloc) * B_ + b;
        float cn = f_ * cS[hb] + i_ * gv;
        float hn = o_ * ftanh(cn);
        cS[hb] = cn;
        if (MODE == 0) {
            g_h1T[(t + 1) & 1][hb] = hn;
        } else {
            g_h2T[(t + 1) & 1][hb] = hn;
            g_h2n[b * H_ + h0 + hloc] = hn;
            g_h2hist[(size_t)t * H_ * B_ + hb] = hn;
        }
    }
    __syncthreads();
}

// ---------------- the single persistent kernel ----------------
__global__ void __launch_bounds__(NTHR, 1)
stdec_kernel(const float* __restrict__ videos,
             const float* __restrict__ h1in, const float* __restrict__ c1in,
             const float* __restrict__ h2in, const float* __restrict__ c2in,
             const float* __restrict__ spatialBias, const float* __restrict__ temporalBias,
             const float* __restrict__ W_h2p, const float* __restrict__ b_h2p,
             const float* __restrict__ W_sC21, const float* __restrict__ b_sC21,
             const float* __restrict__ W_h21, const float* __restrict__ b_h21,
             const float* __restrict__ W_tC21, const float* __restrict__ b_tC21,
             const float* __restrict__ Wih1, const float* __restrict__ Whh1,
             const float* __restrict__ bih1, const float* __restrict__ bhh1,
             const float* __restrict__ Wih2, const float* __restrict__ Whh2,
             const float* __restrict__ bih2, const float* __restrict__ bhh2,
             const float* __restrict__ W_fc, const float* __restrict__ b_fc,
             float* __restrict__ logits_out, float* __restrict__ alphas_out,
             float* __restrict__ betasT_out) {
    extern __shared__ __align__(16) float dsm[];
    const int bid = blockIdx.x, tid = threadIdx.x;
    const int lane = tid & 31, wid = tid >> 5;
    const int gw = bid * NWRP + wid;  // global warp id

    // ---- init states ----
    for (int idx = bid * NTHR + tid; idx < H_ * B_; idx += NBLK * NTHR) {
        int h = idx >> 5, b = idx & 31;
        g_h1T[0][idx] = h1in[h];
        g_h2T[0][idx] = h2in[h];
        g_c1[idx] = c1in[h];
        g_c2[idx] = c2in[h];
        g_h2n[b * H_ + h] = h2in[h];
    }

    // ---- precompute sA2pre / tC2pre (2 tasks per block concurrently) ----
    {
        float* ws = dsm;
        float* wt = dsm + C_;
        for (int i = tid; i < C_; i += NTHR) { ws[i] = W_sC21[i]; wt[i] = W_tC21[i]; }
        __syncthreads();
        float bs0 = b_sC21[0];
        int half = tid >> 8, p = tid & 255;
        for (int task = bid * 2 + half; task < B_ * T_; task += NBLK * 2) {
            int b = task / T_, t = task % T_;
            if (p < P_) {
                const float* vp = videos + ((size_t)(b * T_ + t) * C_) * P_ + p;
                float accs = 0.f, acct = 0.f;
#pragma unroll 8
                for (int c = 0; c < C_; c++) {
                    float v = vp[(size_t)c * P_];
                    accs += v * ws[c];
                    acct += v * wt[c];
                }
                int o = (t * B_ + b) * P_ + p;
                g_sA2pre[o] = accs + bs0 + spatialBias[p];
                g_tC2pre[o] = acct;
            }
        }
        __syncthreads();
    }
    grid_sync();

    // ---- recurrence ----
    for (int t = 0; t < T_; t++) {
        // scores: warp per (b,p) dot; p==196 -> betaH
        for (int task = gw; task < B_ * 197; task += NBLK * NWRP) {
            int b = task / 197, p = task % 197;
            const float4* xr = (const float4*)(g_h2n + b * H_);
            const float4* wr = (const float4*)((p < P_) ? (W_h2p + (size_t)p * H_) : W_h21);
            float acc = 0.f;
#pragma unroll
            for (int j = 0; j < 8; j++) acc += d4(wr[lane + 32 * j], xr[lane + 32 * j]);
            for (int o = 16; o; o >>= 1) acc += __shfl_xor_sync(~0u, acc, o);
            if (lane == 0) {
                if (p < P_)
                    g_sc[b * P_ + p] = acc + b_h2p[p] + g_sA2pre[(t * B_ + b) * P_ + p];
                else
                    g_betaH[b] = acc;
            }
        }
        grid_sync();

        // softmax + alpha/beta out + Y  (blocks 0..127: b = bid>>2, c-chunk = bid&3)
        if (bid < 128) {
            float* sred = dsm;          // [16]
            float* s_alpha = dsm + 16;  // [196]
            int b = bid >> 2, chunk = bid & 3, c0 = chunk * 128;

            float v = (tid < P_) ? g_sc[b * P_ + tid] : -1e30f;
            float m = v;
            for (int o = 16; o; o >>= 1) m = fmaxf(m, __shfl_xor_sync(~0u, m, o));
            if (lane == 0) sred[wid] = m;
            __syncthreads();
            float mAll = sred[0];
#pragma unroll
            for (int i = 1; i < NWRP; i++) mAll = fmaxf(mAll, sred[i]);
            float e = (tid < P_) ? __expf(v - mAll) : 0.f;
            float s = e;
            for (int o = 16; o; o >>= 1) s += __shfl_xor_sync(~0u, s, o);
            __syncthreads();
            if (lane == 0) sred[wid] = s;
            __syncthreads();
            float sAll = sred[0];
#pragma unroll
            for (int i = 1; i < NWRP; i++) sAll += sred[i];
            float a = e / sAll;
            __syncthreads();
            if (tid < P_) {
                s_alpha[tid] = a;
                if (chunk == 0) alphas_out[((size_t)t * B_ + b) * P_ + tid] = a;
            }
            __syncthreads();

            if (chunk == 0) {
                float acc = (tid < P_) ? a * g_tC2pre[(t * B_ + b) * P_ + tid] : 0.f;
                for (int o = 16; o; o >>= 1) acc += __shfl_xor_sync(~0u, acc, o);
                if (lane == 0) sred[wid] = acc;
                __syncthreads();
                if (tid == 0) {
                    float sum = 0.f;
#pragma unroll
                    for (int i = 0; i < NWRP; i++) sum += sred[i];
                    g_beta[t * B_ + b] = sum + g_betaH[b] + b_h21[0] + b_tC21[0] + temporalBias[0];
                }
            }

            // Y: warp per c-row within this block's 128-c chunk
            for (int c = wid; c < 128; c += NWRP) {
                int cg = c0 + c;
                const float* vp = videos + (((size_t)b * T_ + t) * C_ + cg) * P_;
                float acc = 0.f;
                for (int p = lane; p < P_; p += 32) acc += s_alpha[p] * vp[p];
                for (int o = 16; o; o >>= 1) acc += __shfl_xor_sync(~0u, acc, o);
                if (lane == 0) g_YT[cg * B_ + b] = acc;
            }
            __syncthreads();
        }
        grid_sync();

        lstm_phase<0>(t, Wih1, Whh1, bih1, bhh1, dsm);
        grid_sync();
        lstm_phase<1>(t, Wih2, Whh2, bih2, bhh2, dsm);
        grid_sync();
    }

    // ---- betas softmax over time ----
    if (bid == 0 && tid < B_) {
        int b = tid;
        float v[T_];
        float m = -1e30f;
#pragma unroll
        for (int t = 0; t < T_; t++) { v[t] = g_beta[t * B_ + b]; m = fmaxf(m, v[t]); }
        float s = 0.f;
#pragma unroll
        for (int t = 0; t < T_; t++) { v[t] = __expf(v[t] - m); s += v[t]; }
        float inv = 1.f / s;
#pragma unroll
        for (int t = 0; t < T_; t++) {
            float bt = v[t] * inv;
            g_betasT[b * T_ + t] = bt;
            betasT_out[b * T_ + t] = bt;
        }
    }
    grid_sync();

    // ---- hbar[b][h] = sum_t betasT[b][t] * h2hist[t][h][b] ----
    for (int idx = bid * NTHR + tid; idx < H_ * B_; idx += NBLK * NTHR) {
        int h = idx >> 5, b = idx & 31;
        float acc = 0.f;
#pragma unroll
        for (int t = 0; t < T_; t++)
            acc += g_betasT[b * T_ + t] * g_h2hist[(size_t)t * H_ * B_ + h * B_ + b];
        g_hbarN[b * H_ + h] = acc;
    }
    grid_sync();

    // ---- logits: warp per (nc,b) dot over H ----
    for (int task = gw; task < NC_ * B_; task += NBLK * NWRP) {
        int nc = task / B_, b = task % B_;
        const float4* wr = (const float4*)(W_fc + (size_t)nc * H_);
        const float4* xr = (const float4*)(g_hbarN + (size_t)b * H_);
        float acc = 0.f;
#pragma unroll
        for (int j = 0; j < 8; j++) acc += d4(wr[lane + 32 * j], xr[lane + 32 * j]);
        for (int o = 16; o; o >>= 1) acc += __shfl_xor_sync(~0u, acc, o);
        if (lane == 0) logits_out[b * NC_ + nc] = acc + b_fc[nc];
    }
}

// ---------------- launch ----------------
extern "C" void kernel_launch(void* const* d_in, const int* in_sizes, int n_in,
                              void* d_out, int out_size) {
    const float* videos       = (const float*)d_in[0];
    const float* h1           = (const float*)d_in[1];
    const float* c1           = (const float*)d_in[2];
    const float* h2           = (const float*)d_in[3];
    const float* c2           = (const float*)d_in[4];
    const float* spatialBias  = (const float*)d_in[5];
    const float* temporalBias = (const float*)d_in[6];
    const float* W_h2p        = (const float*)d_in[7];
    const float* b_h2p        = (const float*)d_in[8];
    const float* W_sC21       = (const float*)d_in[9];
    const float* b_sC21       = (const float*)d_in[10];
    const float* W_h21        = (const float*)d_in[11];
    const float* b_h21        = (const float*)d_in[12];
    const float* W_tC21       = (const float*)d_in[13];
    const float* b_tC21       = (const float*)d_in[14];
    const float* Wih1         = (const float*)d_in[15];
    const float* Whh1         = (const float*)d_in[16];
    const float* bih1         = (const float*)d_in[17];
    const float* bhh1         = (const float*)d_in[18];
    const float* Wih2         = (const float*)d_in[19];
    const float* Whh2         = (const float*)d_in[20];
    const float* bih2         = (const float*)d_in[21];
    const float* bhh2         = (const float*)d_in[22];
    const float* W_fc         = (const float*)d_in[23];
    const float* b_fc         = (const float*)d_in[24];

    float* out        = (float*)d_out;
    float* logits_out = out;
    float* alphas_out = out + B_ * NC_;
    float* betasT_out = out + B_ * NC_ + (size_t)T_ * B_ * P_;

    cudaFuncSetAttribute(stdec_kernel, cudaFuncAttributeMaxDynamicSharedMemorySize, SMEM_BYTES);
    stdec_kernel<<<NBLK, NTHR, SMEM_BYTES>>>(videos, h1, c1, h2, c2, spatialBias, temporalBias,
                                 W_h2p, b_h2p, W_sC21, b_sC21, W_h21, b_h21, W_tC21, b_tC21,
                                 Wih1, Whh1, bih1, bhh1, Wih2, Whh2, bih2, bhh2,
                                 W_fc, b_fc, logits_out, alphas_out, betasT_out);
}

// round 6
// speedup vs baseline: 4.0390x; 1.0360x over previous
#include <cuda_runtime.h>
#include <math.h>

#define B_  32
#define T_  20
#define C_  512
#define P_  196
#define H_  1024
#define NC_ 101
#define NBLK 148
#define NTHR 512
#define NWRP 16

// LSTM tiling: 16 k-groups (1 warp each), chunk = 16 k, double-buffered
#define NGRP 16
#define CHK 16
#define XSTR 36                       // X tile row stride (floats): [16 k][32 b pad 36]
#define WSTR 20                       // W tile row stride (floats): [32 rows][16 k pad 20]
#define XSZ (CHK * XSTR)              // 576
#define WSZ (32 * WSTR)               // 640
#define GRPSZ (XSZ + WSZ)             // 1216
#define GS_OFF (2 * NGRP * GRPSZ)     // 38912
#define SMEM_FLOATS (GS_OFF + NGRP * 1024)  // + partials [16][32][32] = 55296
#define SMEM_BYTES (SMEM_FLOATS * 4)  // 221184 B

// ---------------- device scratch ----------------
__device__ float g_sA2pre[T_ * B_ * P_];
__device__ float g_tC2pre[T_ * B_ * P_];
__device__ float g_YT[C_ * B_];           // [c][b]
__device__ float g_h1T[2][H_ * B_];       // [h][b] double-buffered
__device__ float g_h2T[2][H_ * B_];
__device__ float g_h2n[B_ * H_];          // [b][h] copy for attention dots
__device__ float g_h2hist[T_ * H_ * B_];
__device__ float g_c1[H_ * B_];
__device__ float g_c2[H_ * B_];
__device__ float g_beta[T_ * B_];
__device__ float g_betasT[B_ * T_];
__device__ float g_hbarN[B_ * H_];
__device__ unsigned g_bar_cnt;
__device__ volatile unsigned g_bar_gen;

__device__ __forceinline__ float sigm(float x) { return 1.0f / (1.0f + __expf(-x)); }
__device__ __forceinline__ float ftanh(float x) { return 1.0f - 2.0f / (__expf(2.0f * x) + 1.0f); }
__device__ __forceinline__ float d4(float4 a, float4 b) {
    return a.x * b.x + a.y * b.y + a.z * b.z + a.w * b.w;
}

// packed fp32x2 ops (FFMA2 — full-rate fp32 on sm_103a)
__device__ __forceinline__ unsigned long long splat2(float w) {
    unsigned long long d; unsigned u = __float_as_uint(w);
    asm("mov.b64 %0, {%1, %1};" : "=l"(d) : "r"(u));
    return d;
}
__device__ __forceinline__ unsigned long long fma2(unsigned long long a, unsigned long long b,
                                                   unsigned long long c) {
    unsigned long long d;
    asm("fma.rn.f32x2 %0, %1, %2, %3;" : "=l"(d) : "l"(a), "l"(b), "l"(c));
    return d;
}

__device__ __forceinline__ void cp16(float* dst, const float* src) {
    unsigned u = (unsigned)__cvta_generic_to_shared(dst);
    asm volatile("cp.async.cg.shared.global [%0], [%1], 16;" :: "r"(u), "l"(src));
}
__device__ __forceinline__ void cp_commit() { asm volatile("cp.async.commit_group;" ::: "memory"); }
__device__ __forceinline__ void cp_wait1()  { asm volatile("cp.async.wait_group 1;" ::: "memory"); }
__device__ __forceinline__ void cp_wait0()  { asm volatile("cp.async.wait_group 0;" ::: "memory"); }

// software grid barrier (all NBLK blocks co-resident)
__device__ __forceinline__ void grid_sync() {
    __syncthreads();
    if (threadIdx.x == 0) {
        __threadfence();
        unsigned gen = g_bar_gen;
        if (atomicAdd(&g_bar_cnt, 1u) == (unsigned)(NBLK - 1)) {
            g_bar_cnt = 0;
            __threadfence();
            g_bar_gen = gen + 1;
        } else {
            while (g_bar_gen == gen) { __nanosleep(64); }
        }
        __threadfence();
    }
    __syncthreads();
}

// ---------------- LSTM: warp-autonomous pipelined GEMM + fused cell ----------------
// 128 blocks; block: 8 h-units (32 gate-rows) x 32 batch. 16 warps = 16 k-slices.
// Each warp: full 32x32 output tile over its K/16 slice; cp.async double-buffered
// 16-k chunks; NO block syncs in mainloop. f32x2 packed over batch pairs.
template <int MODE>
__device__ void lstm_phase(int t,
                           const float* __restrict__ Wih, const float* __restrict__ Whh,
                           const float* __restrict__ bih, const float* __restrict__ bhh,
                           float* dsm) {
    constexpr int K1 = (MODE == 0) ? C_ : H_;
    constexpr int K = K1 + H_;
    constexpr int KG = K / NGRP;     // 96 or 128
    constexpr int NCH = KG / CHK;    // 6 or 8
    const int bid = blockIdx.x, tid = threadIdx.x;
    if (bid >= 128) return;
    const float* __restrict__ X1 = (MODE == 0) ? g_YT : g_h1T[(t + 1) & 1];
    const float* __restrict__ X2 = (MODE == 0) ? g_h1T[t & 1] : g_h2T[t & 1];

    const int h0 = bid * 8;
    const int g = tid >> 5;          // warp = k-group 0..15
    const int lane = tid & 31;
    const int tx = lane & 7;         // batch quad: b = tx*4 .. tx*4+3
    const int trow = lane >> 3;      // rows trow + 4*i, i=0..7

    unsigned long long acc[8][2];
#pragma unroll
    for (int i = 0; i < 8; i++) { acc[i][0] = 0ull; acc[i][1] = 0ull; }

    auto load_chunk = [&](int c, int bufsel) {
        float* Xp = dsm + bufsel * (NGRP * GRPSZ) + g * GRPSZ;
        float* Wp = Xp + XSZ;
        const int kbase = g * KG + c * CHK;
#pragma unroll
        for (int i = 0; i < 4; i++) {               // X: [16 k][32 b]
            int f = lane + 32 * i;
            int kk = f >> 3, bq = f & 7;
            int kg2 = kbase + kk;
            const float* src = (kg2 < K1) ? (X1 + kg2 * B_ + bq * 4)
                                          : (X2 + (kg2 - K1) * B_ + bq * 4);
            cp16(Xp + kk * XSTR + bq * 4, src);
        }
#pragma unroll
        for (int i = 0; i < 4; i++) {               // W: [32 rows][16 k]
            int f = lane + 32 * i;
            int row = f >> 2, kq = f & 3;
            int kg2 = kbase + kq * 4;
            int grow = (row >> 3) * H_ + h0 + (row & 7);
            const float* src = (kg2 < K1) ? (Wih + (size_t)grow * K1 + kg2)
                                          : (Whh + (size_t)grow * H_ + (kg2 - K1));
            cp16(Wp + row * WSTR + kq * 4, src);
        }
    };

    load_chunk(0, 0);
    cp_commit();

    for (int c = 0; c < NCH; c++) {
        if (c + 1 < NCH) { load_chunk(c + 1, (c + 1) & 1); cp_commit(); cp_wait1(); }
        else { cp_wait0(); }

        const float* Xp = dsm + (c & 1) * (NGRP * GRPSZ) + g * GRPSZ;
        const float* Wp = Xp + XSZ;
#pragma unroll
        for (int kk = 0; kk < CHK; kk += 4) {
            float4 wq[8];
            ulonglong2 xq[4];
#pragma unroll
            for (int i = 0; i < 8; i++)
                wq[i] = *(const float4*)&Wp[(trow + 4 * i) * WSTR + kk];
#pragma unroll
            for (int r = 0; r < 4; r++)
                xq[r] = *(const ulonglong2*)&Xp[(kk + r) * XSTR + tx * 4];
#pragma unroll
            for (int r = 0; r < 4; r++) {
                const float* wf;
#pragma unroll
                for (int i = 0; i < 8; i++) {
                    wf = (const float*)&wq[i];
                    unsigned long long w2 = splat2(wf[r]);
                    acc[i][0] = fma2(w2, xq[r].x, acc[i][0]);
                    acc[i][1] = fma2(w2, xq[r].y, acc[i][1]);
                }
            }
        }
    }

    // partials to smem, then fused bias + cell update
    float* Gs = dsm + GS_OFF;  // [16 g][32 rows][32 b]
#pragma unroll
    for (int i = 0; i < 8; i++) {
        ulonglong2 uv; uv.x = acc[i][0]; uv.y = acc[i][1];
        *(ulonglong2*)&Gs[g * 1024 + (trow + 4 * i) * 32 + tx * 4] = uv;
    }
    __syncthreads();

    if (tid < 256) {
        int u = tid >> 5, b = tid & 31;
        float gate[4];
#pragma unroll
        for (int q = 0; q < 4; q++) {
            int l = q * 8 + u;
            int row = q * H_ + h0 + u;
            float s = bih[row] + bhh[row];
#pragma unroll
            for (int gg = 0; gg < NGRP; gg++) s += Gs[gg * 1024 + l * 32 + b];
            gate[q] = s;
        }
        float i_ = sigm(gate[0]), f_ = sigm(gate[1]), gv = ftanh(gate[2]), o_ = sigm(gate[3]);
        float* cS = (MODE == 0) ? g_c1 : g_c2;
        int hb = (h0 + u) * B_ + b;
        float cn = f_ * cS[hb] + i_ * gv;
        float hn = o_ * ftanh(cn);
        cS[hb] = cn;
        if (MODE == 0) {
            g_h1T[(t + 1) & 1][hb] = hn;
        } else {
            g_h2T[(t + 1) & 1][hb] = hn;
            g_h2n[b * H_ + h0 + u] = hn;
            g_h2hist[(size_t)t * H_ * B_ + hb] = hn;
        }
    }
    __syncthreads();
}

// ---------------- the single persistent kernel ----------------
__global__ void __launch_bounds__(NTHR, 1)
stdec_kernel(const float* __restrict__ videos,
             const float* __restrict__ h1in, const float* __restrict__ c1in,
             const float* __restrict__ h2in, const float* __restrict__ c2in,
             const float* __restrict__ spatialBias, const float* __restrict__ temporalBias,
             const float* __restrict__ W_h2p, const float* __restrict__ b_h2p,
             const float* __restrict__ W_sC21, const float* __restrict__ b_sC21,
             const float* __restrict__ W_h21, const float* __restrict__ b_h21,
             const float* __restrict__ W_tC21, const float* __restrict__ b_tC21,
             const float* __restrict__ Wih1, const float* __restrict__ Whh1,
             const float* __restrict__ bih1, const float* __restrict__ bhh1,
             const float* __restrict__ Wih2, const float* __restrict__ Whh2,
             const float* __restrict__ bih2, const float* __restrict__ bhh2,
             const float* __restrict__ W_fc, const float* __restrict__ b_fc,
             float* __restrict__ logits_out, float* __restrict__ alphas_out,
             float* __restrict__ betasT_out) {
    extern __shared__ __align__(16) float dsm[];
    const int bid = blockIdx.x, tid = threadIdx.x;
    const int lane = tid & 31, wid = tid >> 5;
    const int gw = bid * NWRP + wid;

    // ---- init states ----
    for (int idx = bid * NTHR + tid; idx < H_ * B_; idx += NBLK * NTHR) {
        int h = idx >> 5, b = idx & 31;
        g_h1T[0][idx] = h1in[h];
        g_h2T[0][idx] = h2in[h];
        g_c1[idx] = c1in[h];
        g_c2[idx] = c2in[h];
        g_h2n[b * H_ + h] = h2in[h];
    }

    // ---- precompute sA2pre / tC2pre (2 tasks per block) ----
    {
        float* ws = dsm;
        float* wt = dsm + C_;
        for (int i = tid; i < C_; i += NTHR) { ws[i] = W_sC21[i]; wt[i] = W_tC21[i]; }
        __syncthreads();
        float bs0 = b_sC21[0];
        int half = tid >> 8, p = tid & 255;
        for (int task = bid * 2 + half; task < B_ * T_; task += NBLK * 2) {
            int b = task / T_, t = task % T_;
            if (p < P_) {
                const float* vp = videos + ((size_t)(b * T_ + t) * C_) * P_ + p;
                float accs = 0.f, acct = 0.f;
#pragma unroll 8
                for (int c = 0; c < C_; c++) {
                    float v = vp[(size_t)c * P_];
                    accs += v * ws[c];
                    acct += v * wt[c];
                }
                int o = (t * B_ + b) * P_ + p;
                g_sA2pre[o] = accs + bs0 + spatialBias[p];
                g_tC2pre[o] = acct;
            }
        }
        __syncthreads();
    }
    grid_sync();

    // ---- recurrence: 3 phases / 3 barriers per step ----
    for (int t = 0; t < T_; t++) {
        // fused attention: scores + softmax + beta + Y (blocks 0..127)
        if (bid < 128) {
            float* h2s     = dsm;            // [1024]
            float* sc      = dsm + 1024;     // [200] (196 scores + slot 196 = W_h21 dot)
            float* sred    = dsm + 1232;     // [16]
            float* s_alpha = dsm + 1248;     // [196]
            int b = bid >> 2, chunk = bid & 3, c0 = chunk * 128;

            for (int i = tid; i < H_; i += NTHR) h2s[i] = g_h2n[b * H_ + i];
            __syncthreads();

            const float4* xr = (const float4*)h2s;
            for (int p = wid; p < 197; p += NWRP) {
                const float4* wr = (const float4*)((p < P_) ? (W_h2p + (size_t)p * H_) : W_h21);
                float acc = 0.f;
#pragma unroll
                for (int j = 0; j < 8; j++) acc += d4(wr[lane + 32 * j], xr[lane + 32 * j]);
                for (int o = 16; o; o >>= 1) acc += __shfl_xor_sync(~0u, acc, o);
                if (lane == 0)
                    sc[p] = (p < P_) ? (acc + b_h2p[p] + g_sA2pre[(t * B_ + b) * P_ + p]) : acc;
            }
            __syncthreads();

            // softmax over 196
            float v = (tid < P_) ? sc[tid] : -1e30f;
            float m = v;
            for (int o = 16; o; o >>= 1) m = fmaxf(m, __shfl_xor_sync(~0u, m, o));
            if (lane == 0) sred[wid] = m;
            __syncthreads();
            float mAll = sred[0];
#pragma unroll
            for (int i = 1; i < NWRP; i++) mAll = fmaxf(mAll, sred[i]);
            float e = (tid < P_) ? __expf(v - mAll) : 0.f;
            float s = e;
            for (int o = 16; o; o >>= 1) s += __shfl_xor_sync(~0u, s, o);
            __syncthreads();
            if (lane == 0) sred[wid] = s;
            __syncthreads();
            float sAll = sred[0];
#pragma unroll
            for (int i = 1; i < NWRP; i++) sAll += sred[i];
            float a = e / sAll;
            __syncthreads();
            if (tid < P_) {
                s_alpha[tid] = a;
                if (chunk == 0) alphas_out[((size_t)t * B_ + b) * P_ + tid] = a;
            }
            __syncthreads();

            if (chunk == 0) {
                float acc = (tid < P_) ? a * g_tC2pre[(t * B_ + b) * P_ + tid] : 0.f;
                for (int o = 16; o; o >>= 1) acc += __shfl_xor_sync(~0u, acc, o);
                if (lane == 0) sred[wid] = acc;
                __syncthreads();
                if (tid == 0) {
                    float sum = 0.f;
#pragma unroll
                    for (int i = 0; i < NWRP; i++) sum += sred[i];
                    g_beta[t * B_ + b] = sum + sc[196] + b_h21[0] + b_tC21[0] + temporalBias[0];
                }
            }

            // Y: warp per c-row within this block's 128-c chunk
            for (int c = wid; c < 128; c += NWRP) {
                int cg = c0 + c;
                const float* vp = videos + (((size_t)b * T_ + t) * C_ + cg) * P_;
                float acc = 0.f;
                for (int p = lane; p < P_; p += 32) acc += s_alpha[p] * vp[p];
                for (int o = 16; o; o >>= 1) acc += __shfl_xor_sync(~0u, acc, o);
                if (lane == 0) g_YT[cg * B_ + b] = acc;
            }
        }
        grid_sync();

        lstm_phase<0>(t, Wih1, Whh1, bih1, bhh1, dsm);
        grid_sync();
        lstm_phase<1>(t, Wih2, Whh2, bih2, bhh2, dsm);
        grid_sync();
    }

    // ---- betas softmax over time ----
    if (bid == 0 && tid < B_) {
        int b = tid;
        float v[T_];
        float m = -1e30f;
#pragma unroll
        for (int t = 0; t < T_; t++) { v[t] = g_beta[t * B_ + b]; m = fmaxf(m, v[t]); }
        float s = 0.f;
#pragma unroll
        for (int t = 0; t < T_; t++) { v[t] = __expf(v[t] - m); s += v[t]; }
        float inv = 1.f / s;
#pragma unroll
        for (int t = 0; t < T_; t++) {
            float bt = v[t] * inv;
            g_betasT[b * T_ + t] = bt;
            betasT_out[b * T_ + t] = bt;
        }
    }
    grid_sync();

    // ---- hbar[b][h] = sum_t betasT[b][t] * h2hist[t][h][b] ----
    for (int idx = bid * NTHR + tid; idx < H_ * B_; idx += NBLK * NTHR) {
        int h = idx >> 5, b = idx & 31;
        float acc = 0.f;
#pragma unroll
        for (int t = 0; t < T_; t++)
            acc += g_betasT[b * T_ + t] * g_h2hist[(size_t)t * H_ * B_ + h * B_ + b];
        g_hbarN[b * H_ + h] = acc;
    }
    grid_sync();

    // ---- logits: warp per (nc,b) dot over H ----
    for (int task = gw; task < NC_ * B_; task += NBLK * NWRP) {
        int nc = task / B_, b = task % B_;
        const float4* wr = (const float4*)(W_fc + (size_t)nc * H_);
        const float4* xr = (const float4*)(g_hbarN + (size_t)b * H_);
        float acc = 0.f;
#pragma unroll
        for (int j = 0; j < 8; j++) acc += d4(wr[lane + 32 * j], xr[lane + 32 * j]);
        for (int o = 16; o; o >>= 1) acc += __shfl_xor_sync(~0u, acc, o);
        if (lane == 0) logits_out[b * NC_ + nc] = acc + b_fc[nc];
    }
}

// ---------------- launch ----------------
extern "C" void kernel_launch(void* const* d_in, const int* in_sizes, int n_in,
                              void* d_out, int out_size) {
    const float* videos       = (const float*)d_in[0];
    const float* h1           = (const float*)d_in[1];
    const float* c1           = (const float*)d_in[2];
    const float* h2           = (const float*)d_in[3];
    const float* c2           = (const float*)d_in[4];
    const float* spatialBias  = (const float*)d_in[5];
    const float* temporalBias = (const float*)d_in[6];
    const float* W_h2p        = (const float*)d_in[7];
    const float* b_h2p        = (const float*)d_in[8];
    const float* W_sC21       = (const float*)d_in[9];
    const float* b_sC21       = (const float*)d_in[10];
    const float* W_h21        = (const float*)d_in[11];
    const float* b_h21        = (const float*)d_in[12];
    const float* W_tC21       = (const float*)d_in[13];
    const float* b_tC21       = (const float*)d_in[14];
    const float* Wih1         = (const float*)d_in[15];
    const float* Whh1         = (const float*)d_in[16];
    const float* bih1         = (const float*)d_in[17];
    const float* bhh1         = (const float*)d_in[18];
    const float* Wih2         = (const float*)d_in[19];
    const float* Whh2         = (const float*)d_in[20];
    const float* bih2         = (const float*)d_in[21];
    const float* bhh2         = (const float*)d_in[22];
    const float* W_fc         = (const float*)d_in[23];
    const float* b_fc         = (const float*)d_in[24];

    float* out        = (float*)d_out;
    float* logits_out = out;
    float* alphas_out = out + B_ * NC_;
    float* betasT_out = out + B_ * NC_ + (size_t)T_ * B_ * P_;

    cudaFuncSetAttribute(stdec_kernel, cudaFuncAttributeMaxDynamicSharedMemorySize, SMEM_BYTES);
    stdec_kernel<<<NBLK, NTHR, SMEM_BYTES>>>(videos, h1, c1, h2, c2, spatialBias, temporalBias,
                                 W_h2p, b_h2p, W_sC21, b_sC21, W_h21, b_h21, W_tC21, b_tC21,
                                 Wih1, Whh1, bih1, bhh1, Wih2, Whh2, bih2, bhh2,
                                 W_fc, b_fc, logits_out, alphas_out, betasT_out);
}